// round 17
// baseline (speedup 1.0000x reference)
#include <cuda_runtime.h>
#include <cuda_fp16.h>

#define N_NODES 100000
#define N_EDGES 3200000
#define HID 64
#define ELL 112   // multiple of 16; deg ~ Poisson(32), P(>=112) ~ 0

#define GEMM_BLOCKS 1563          // 64 rows per block
#define SCAT_BLOCKS 1563          // 2048 edges per block (256 thr x 8 edges)
#define PREP_GRID (2 * GEMM_BLOCKS)   // even: gemm1, odd: scatter

// ---------------- device scratch (no allocation allowed) -------------------
__device__ __half g_h1[N_NODES * HID];   // gemm1 output (fp16)
__device__ __half g_h2[N_NODES * HID];   // fused spmm1+gemm2 output (fp16)
__device__ int    g_cnt[N_NODES];        // zero-init; reset by spmm2 each run
__device__ unsigned g_cv[(size_t)N_NODES * ELL + 16];  // (fp16val<<17)|col, +pad

// ---------------------------------------------------------------------------
// mma/ldmatrix helpers
// ---------------------------------------------------------------------------
__device__ __forceinline__ unsigned sptr(const void* p) {
    return (unsigned)__cvta_generic_to_shared(p);
}
__device__ __forceinline__ void ldm_x4(unsigned& a0, unsigned& a1,
                                       unsigned& a2, unsigned& a3, unsigned addr) {
    asm volatile("ldmatrix.sync.aligned.m8n8.x4.shared.b16 {%0,%1,%2,%3}, [%4];"
                 : "=r"(a0), "=r"(a1), "=r"(a2), "=r"(a3) : "r"(addr));
}
__device__ __forceinline__ void ldm_x2(unsigned& b0, unsigned& b1, unsigned addr) {
    asm volatile("ldmatrix.sync.aligned.m8n8.x2.shared.b16 {%0,%1}, [%2];"
                 : "=r"(b0), "=r"(b1) : "r"(addr));
}
__device__ __forceinline__ void mma16816(float* c, unsigned a0, unsigned a1,
                                         unsigned a2, unsigned a3,
                                         unsigned b0, unsigned b1) {
    asm volatile(
        "mma.sync.aligned.m16n8k16.row.col.f32.f16.f16.f32 "
        "{%0,%1,%2,%3}, {%4,%5,%6,%7}, {%8,%9}, {%0,%1,%2,%3};"
        : "+f"(c[0]), "+f"(c[1]), "+f"(c[2]), "+f"(c[3])
        : "r"(a0), "r"(a1), "r"(a2), "r"(a3), "r"(b0), "r"(b1));
}

// ---------------------------------------------------------------------------
// prep: interleaved scatter (odd blocks, 8 edges/thread, all loads hoisted) +
//       HMMA gemm1 (even blocks)
// ---------------------------------------------------------------------------
__global__ void prep_kernel(const int* __restrict__ rowi,
                            const int* __restrict__ coli,
                            const float* __restrict__ vals,
                            const float* __restrict__ emb,
                            const float* __restrict__ deg,
                            const float* __restrict__ seed,
                            const float* __restrict__ W1,
                            const float* __restrict__ b1) {
    __shared__ __align__(16) __half xs[64][136];   // emb fp16 (128 used + pad)
    __shared__ __align__(16) __half Wns[64][136];  // W1T fp16: [n][k], k<128
    __shared__ float extw0[64], extw1[64], b1s[64], degs[64], seeds[64];
    int t = threadIdx.x;

    if (blockIdx.x & 1) {
        // ------- scatter into ELL: 8 edges/thread (N_EDGES % 8 == 0) -------
        int sbid = blockIdx.x >> 1;
        int base = sbid * 2048 + t * 8;
        if (base >= N_EDGES) return;

        uint4  ra = __ldg((const uint4*)(rowi + base));
        uint4  rb = __ldg((const uint4*)(rowi + base + 4));
        uint4  ca = __ldg((const uint4*)(coli + base));
        uint4  cb = __ldg((const uint4*)(coli + base + 4));
        float4 va = __ldg((const float4*)(vals + base));
        float4 vb = __ldg((const float4*)(vals + base + 4));

        int s0 = atomicAdd(&g_cnt[(int)ra.x], 1);
        int s1 = atomicAdd(&g_cnt[(int)ra.y], 1);
        int s2 = atomicAdd(&g_cnt[(int)ra.z], 1);
        int s3 = atomicAdd(&g_cnt[(int)ra.w], 1);
        int s4 = atomicAdd(&g_cnt[(int)rb.x], 1);
        int s5 = atomicAdd(&g_cnt[(int)rb.y], 1);
        int s6 = atomicAdd(&g_cnt[(int)rb.z], 1);
        int s7 = atomicAdd(&g_cnt[(int)rb.w], 1);

        unsigned h0 = __half_as_ushort(__float2half_rn(va.x));
        unsigned h1 = __half_as_ushort(__float2half_rn(va.y));
        unsigned h2 = __half_as_ushort(__float2half_rn(va.z));
        unsigned h3 = __half_as_ushort(__float2half_rn(va.w));
        unsigned h4 = __half_as_ushort(__float2half_rn(vb.x));
        unsigned h5 = __half_as_ushort(__float2half_rn(vb.y));
        unsigned h6 = __half_as_ushort(__float2half_rn(vb.z));
        unsigned h7 = __half_as_ushort(__float2half_rn(vb.w));

        if (s0 < ELL) g_cv[(size_t)ra.x * ELL + s0] = (h0 << 17) | ca.x;
        if (s1 < ELL) g_cv[(size_t)ra.y * ELL + s1] = (h1 << 17) | ca.y;
        if (s2 < ELL) g_cv[(size_t)ra.z * ELL + s2] = (h2 << 17) | ca.z;
        if (s3 < ELL) g_cv[(size_t)ra.w * ELL + s3] = (h3 << 17) | ca.w;
        if (s4 < ELL) g_cv[(size_t)rb.x * ELL + s4] = (h4 << 17) | cb.x;
        if (s5 < ELL) g_cv[(size_t)rb.y * ELL + s5] = (h5 << 17) | cb.y;
        if (s6 < ELL) g_cv[(size_t)rb.z * ELL + s6] = (h6 << 17) | cb.z;
        if (s7 < ELL) g_cv[(size_t)rb.w * ELL + s7] = (h7 << 17) | cb.w;
        return;
    }

    // ---------------- gemm1 via HMMA ----------------
    int n0 = (blockIdx.x >> 1) * 64;

    #pragma unroll
    for (int i = 0; i < 8; i++) {
        int idx = t + i * 256;
        int r = idx >> 5, q = idx & 31;
        int node = n0 + r;
        float4 v = (node < N_NODES)
                       ? __ldg((const float4*)(emb + (size_t)node * 128) + q)
                       : make_float4(0.f, 0.f, 0.f, 0.f);
        __half2 h0 = __floats2half2_rn(v.x, v.y);
        __half2 h1 = __floats2half2_rn(v.z, v.w);
        *(uint2*)&xs[r][q * 4] = make_uint2(*(unsigned*)&h0, *(unsigned*)&h1);
    }
    #pragma unroll
    for (int i = 0; i < 32; i++) {
        int idx = t + i * 256;
        int k = idx >> 6, n = idx & 63;
        Wns[n][k] = __float2half_rn(__ldg(W1 + k * 64 + n));
    }
    if (t < 64) {
        extw0[t] = __ldg(W1 + 128 * 64 + t);
        extw1[t] = __ldg(W1 + 129 * 64 + t);
        b1s[t] = __ldg(b1 + t);
        int node = n0 + t;
        degs[t] = (node < N_NODES) ? __ldg(deg + node) : 0.f;
        seeds[t] = (node < N_NODES) ? __ldg(seed + node) : 0.f;
    }
    __syncthreads();

    int w = t >> 5, lane = t & 31;
    int mt = w >> 1, nh = w & 1;
    float acc[4][4];
    #pragma unroll
    for (int i = 0; i < 4; i++)
        #pragma unroll
        for (int j = 0; j < 4; j++) acc[i][j] = 0.f;

    unsigned Abase = sptr(&xs[mt * 16][0]);
    unsigned Bbase = sptr(&Wns[nh * 32][0]);
    #pragma unroll
    for (int ks = 0; ks < 8; ks++) {
        unsigned a0, a1, a2, a3;
        ldm_x4(a0, a1, a2, a3,
               Abase + (lane & 15) * 272 + ks * 32 + (lane >> 4) * 16);
        #pragma unroll
        for (int nt = 0; nt < 4; nt++) {
            unsigned b0, b1v;
            ldm_x2(b0, b1v,
                   Bbase + (nt * 8 + (lane & 7)) * 272 + ks * 32 + ((lane >> 3) & 1) * 16);
            mma16816(acc[nt], a0, a1, a2, a3, b0, b1v);
        }
    }

    int r0 = mt * 16 + (lane >> 2);
    int r1 = r0 + 8;
    float d0 = degs[r0], s0 = seeds[r0], d1 = degs[r1], s1v = seeds[r1];
    int gr0 = n0 + r0, gr1 = n0 + r1;
    #pragma unroll
    for (int nt = 0; nt < 4; nt++) {
        int c = nh * 32 + nt * 8 + (lane & 3) * 2;
        float ea = extw0[c], eb = extw0[c + 1];
        float fa = extw1[c], fb = extw1[c + 1];
        float ba = b1s[c], bb = b1s[c + 1];
        if (gr0 < N_NODES) {
            __half2 h = __floats2half2_rn(acc[nt][0] + d0 * ea + s0 * fa + ba,
                                          acc[nt][1] + d0 * eb + s0 * fb + bb);
            *(unsigned*)&g_h1[gr0 * 64 + c] = *(unsigned*)&h;
        }
        if (gr1 < N_NODES) {
            __half2 h = __floats2half2_rn(acc[nt][2] + d1 * ea + s1v * fa + ba,
                                          acc[nt][3] + d1 * eb + s1v * fb + bb);
            *(unsigned*)&g_h1[gr1 * 64 + c] = *(unsigned*)&h;
        }
    }
}

// ---------------------------------------------------------------------------
// Gather core: warp-per-row, 8 lanes/edge, 16 edges/iter, cv software-pipelined.
// ---------------------------------------------------------------------------
__device__ __forceinline__ void gather_row(const __half* Xh, int r, int lane,
                                           float* acc) {
    int dg = min(g_cnt[r], ELL);
    int deg16 = (dg + 15) & ~15;
    const unsigned* __restrict__ cvp = g_cv + (size_t)r * ELL + (lane >> 3);
    const char* __restrict__ xbase = (const char*)Xh + (lane & 7) * 16;

    unsigned c0 = __ldg(cvp), c1 = __ldg(cvp + 4);
    unsigned c2 = __ldg(cvp + 8), c3 = __ldg(cvp + 12);

    for (int e = 0; e < deg16; e += 16) {
        uint4 p0 = __ldg((const uint4*)(xbase + ((c0 & 0x1FFFFu) << 7)));
        uint4 p1 = __ldg((const uint4*)(xbase + ((c1 & 0x1FFFFu) << 7)));
        uint4 p2 = __ldg((const uint4*)(xbase + ((c2 & 0x1FFFFu) << 7)));
        uint4 p3 = __ldg((const uint4*)(xbase + ((c3 & 0x1FFFFu) << 7)));
        unsigned u0 = __byte_perm(c0 >> 17, 0, 0x1010);
        unsigned u1 = __byte_perm(c1 >> 17, 0, 0x1010);
        unsigned u2 = __byte_perm(c2 >> 17, 0, 0x1010);
        unsigned u3 = __byte_perm(c3 >> 17, 0, 0x1010);
        c0 = __ldg(cvp + e + 16); c1 = __ldg(cvp + e + 20);
        c2 = __ldg(cvp + e + 24); c3 = __ldg(cvp + e + 28);
        __half2 v0 = *(__half2*)&u0, v1 = *(__half2*)&u1;
        __half2 v2 = *(__half2*)&u2, v3 = *(__half2*)&u3;

        __half2 h0 = __hmul2(*(const __half2*)&p0.x, v0);
        __half2 h1 = __hmul2(*(const __half2*)&p0.y, v0);
        __half2 h2 = __hmul2(*(const __half2*)&p0.z, v0);
        __half2 h3 = __hmul2(*(const __half2*)&p0.w, v0);
        h0 = __hfma2(*(const __half2*)&p1.x, v1, h0);
        h1 = __hfma2(*(const __half2*)&p1.y, v1, h1);
        h2 = __hfma2(*(const __half2*)&p1.z, v1, h2);
        h3 = __hfma2(*(const __half2*)&p1.w, v1, h3);
        h0 = __hfma2(*(const __half2*)&p2.x, v2, h0);
        h1 = __hfma2(*(const __half2*)&p2.y, v2, h1);
        h2 = __hfma2(*(const __half2*)&p2.z, v2, h2);
        h3 = __hfma2(*(const __half2*)&p2.w, v2, h3);
        h0 = __hfma2(*(const __half2*)&p3.x, v3, h0);
        h1 = __hfma2(*(const __half2*)&p3.y, v3, h1);
        h2 = __hfma2(*(const __half2*)&p3.z, v3, h2);
        h3 = __hfma2(*(const __half2*)&p3.w, v3, h3);

        float2 f;
        f = __half22float2(h0); acc[0] += f.x; acc[1] += f.y;
        f = __half22float2(h1); acc[2] += f.x; acc[3] += f.y;
        f = __half22float2(h2); acc[4] += f.x; acc[5] += f.y;
        f = __half22float2(h3); acc[6] += f.x; acc[7] += f.y;
    }

    #pragma unroll
    for (int i = 0; i < 8; i++) {
        acc[i] += __shfl_xor_sync(0xffffffffu, acc[i], 8);
        acc[i] += __shfl_xor_sync(0xffffffffu, acc[i], 16);
    }
}

// ---------------------------------------------------------------------------
// SpMM1 + GEMM2 fused (64 rows/block): relu(A@h1) -> smem, then HMMA @W2+b2
// Block 0 thread 0 also initializes out = bout (spmm2's atomics come later).
// ---------------------------------------------------------------------------
__global__ void spmm1g2_kernel(const float* __restrict__ W2,
                               const float* __restrict__ b2,
                               const float* __restrict__ bout, float* out) {
    __shared__ __align__(16) __half xs[64][72];    // relu(s1) tile
    __shared__ __align__(16) __half Wns[64][72];   // W2T fp16 [n][k]
    __shared__ float b2s[64];
    int t = threadIdx.x;
    int n0 = blockIdx.x * 64;
    if (blockIdx.x == 0 && t == 0) out[0] = __ldg(bout);

    #pragma unroll
    for (int i = 0; i < 16; i++) {
        int idx = t + i * 256;
        int k = idx >> 6, n = idx & 63;
        Wns[n][k] = __float2half_rn(__ldg(W2 + k * 64 + n));
    }
    if (t < 64) b2s[t] = __ldg(b2 + t);

    int w = t >> 5, lane = t & 31;

    #pragma unroll 1
    for (int i = 0; i < 8; i++) {
        int rl = w * 8 + i;
        int r = n0 + rl;
        float acc[8] = {0.f, 0.f, 0.f, 0.f, 0.f, 0.f, 0.f, 0.f};
        if (r < N_NODES) gather_row(g_h1, r, lane, acc);
        if (lane < 8) {
            __half2 h0 = __floats2half2_rn(fmaxf(acc[0], 0.f), fmaxf(acc[1], 0.f));
            __half2 h1 = __floats2half2_rn(fmaxf(acc[2], 0.f), fmaxf(acc[3], 0.f));
            __half2 h2 = __floats2half2_rn(fmaxf(acc[4], 0.f), fmaxf(acc[5], 0.f));
            __half2 h3 = __floats2half2_rn(fmaxf(acc[6], 0.f), fmaxf(acc[7], 0.f));
            *(uint4*)&xs[rl][lane * 8] = make_uint4(*(unsigned*)&h0, *(unsigned*)&h1,
                                                    *(unsigned*)&h2, *(unsigned*)&h3);
        }
    }
    __syncthreads();

    int mt = w >> 1, nh = w & 1;
    float acc[4][4];
    #pragma unroll
    for (int i = 0; i < 4; i++)
        #pragma unroll
        for (int j = 0; j < 4; j++) acc[i][j] = 0.f;

    unsigned Abase = sptr(&xs[mt * 16][0]);
    unsigned Bbase = sptr(&Wns[nh * 32][0]);
    #pragma unroll
    for (int ks = 0; ks < 4; ks++) {
        unsigned a0, a1, a2, a3;
        ldm_x4(a0, a1, a2, a3,
               Abase + (lane & 15) * 144 + ks * 32 + (lane >> 4) * 16);
        #pragma unroll
        for (int nt = 0; nt < 4; nt++) {
            unsigned b0, b1v;
            ldm_x2(b0, b1v,
                   Bbase + (nt * 8 + (lane & 7)) * 144 + ks * 32 + ((lane >> 3) & 1) * 16);
            mma16816(acc[nt], a0, a1, a2, a3, b0, b1v);
        }
    }

    int r0 = mt * 16 + (lane >> 2);
    int gr0 = n0 + r0, gr1 = gr0 + 8;
    #pragma unroll
    for (int nt = 0; nt < 4; nt++) {
        int c = nh * 32 + nt * 8 + (lane & 3) * 2;
        float ba = b2s[c], bb = b2s[c + 1];
        if (gr0 < N_NODES) {
            __half2 h = __floats2half2_rn(acc[nt][0] + ba, acc[nt][1] + bb);
            *(unsigned*)&g_h2[gr0 * 64 + c] = *(unsigned*)&h;
        }
        if (gr1 < N_NODES) {
            __half2 h = __floats2half2_rn(acc[nt][2] + ba, acc[nt][3] + bb);
            *(unsigned*)&g_h2[gr1 * 64 + c] = *(unsigned*)&h;
        }
    }
}

// ---------------------------------------------------------------------------
// SpMM2 + final projection: out += sum_r dot(relu(A @ h2)[r], Wout).
// Also resets g_cnt[r] = 0 for the next graph replay (last consumer).
// ---------------------------------------------------------------------------
__global__ void spmm2_kernel(const float* __restrict__ Wout, float* out) {
    __shared__ float wsum[8];
    int t = threadIdx.x;
    int w = t >> 5, lane = t & 31;
    int r = blockIdx.x * 8 + w;

    float acc[8] = {0.f, 0.f, 0.f, 0.f, 0.f, 0.f, 0.f, 0.f};
    gather_row(g_h2, r, lane, acc);
    if (lane == 0) g_cnt[r] = 0;     // reset for next replay (warp converged)

    float4 wo0 = __ldg((const float4*)Wout + (lane & 7) * 2);
    float4 wo1 = __ldg((const float4*)Wout + (lane & 7) * 2 + 1);
    float p = fmaxf(acc[0], 0.f) * wo0.x + fmaxf(acc[1], 0.f) * wo0.y +
              fmaxf(acc[2], 0.f) * wo0.z + fmaxf(acc[3], 0.f) * wo0.w +
              fmaxf(acc[4], 0.f) * wo1.x + fmaxf(acc[5], 0.f) * wo1.y +
              fmaxf(acc[6], 0.f) * wo1.z + fmaxf(acc[7], 0.f) * wo1.w;
    if (lane >= 8) p = 0.f;

    #pragma unroll
    for (int o = 16; o > 0; o >>= 1) p += __shfl_down_sync(0xffffffffu, p, o);
    if (lane == 0) wsum[w] = p;
    __syncthreads();
    if (t < 8) {
        float s = wsum[t];
        #pragma unroll
        for (int o = 4; o > 0; o >>= 1) s += __shfl_down_sync(0xffu, s, o);
        if (t == 0) atomicAdd(out, s);
    }
}

// ---------------------------------------------------------------------------
extern "C" void kernel_launch(void* const* d_in, const int* in_sizes, int n_in,
                              void* d_out, int out_size) {
    const float* emb   = (const float*)d_in[0];
    const float* deg   = (const float*)d_in[1];
    const float* seed  = (const float*)d_in[2];
    const int*   arow  = (const int*)d_in[3];
    const int*   acol  = (const int*)d_in[4];
    const float* avals = (const float*)d_in[5];
    const float* W1    = (const float*)d_in[6];
    const float* b1    = (const float*)d_in[7];
    const float* W2    = (const float*)d_in[8];
    const float* b2    = (const float*)d_in[9];
    const float* Wout  = (const float*)d_in[10];
    const float* bout  = (const float*)d_in[11];
    float* out = (float*)d_out;

    prep_kernel<<<PREP_GRID, 256>>>(arow, acol, avals, emb, deg, seed, W1, b1);
    spmm1g2_kernel<<<GEMM_BLOCKS, 256>>>(W2, b2, bout, out);
    spmm2_kernel<<<N_NODES / 8, 256>>>(Wout, out);
}